// round 16
// baseline (speedup 1.0000x reference)
#include <cuda_runtime.h>
#include <cuda_fp16.h>
#include <cstdint>

// ============================================================================
// MHMLP: out[b,h] = lrelu( sum_n lrelu( x[b,:]·W1[h,:,n] + b1[h,n] ) * W2[h,n] + b2[h] )
// B=2048, H=64, D=512(K), HID=2048(N). fp32 in/out, fp16 HMMA (rt8/SMSP).
// R16 = champion R5 + DE-PHASED FOLDS: half 1 folds at bottom of kb==7 (as
// before); half 0 defers its fold to the TOP of the next chunk's kb==0
// iteration (+ one post-loop fold). Fold lumps of the two halves never
// coincide -> the other half's MMA stream covers the tensor-pipe hole.
// bw (b1,W2) table in smem (LDS 29cyc) instead of global float4 (L2 ~240cyc).
// ============================================================================
#define BB   2048
#define HH   64
#define DD   512
#define HID  2048

__device__ __half  g_W16[(size_t)HH * DD * HID];    // [h][d][n] fp16
__device__ __half  g_X16[(size_t)BB * DD];          // [b][d]   fp16

__device__ __forceinline__ uint32_t smem_to_u32(const void* p) {
    uint32_t a;
    asm("{ .reg .u64 t; cvta.to.shared.u64 t, %1; cvt.u32.u64 %0, t; }" : "=r"(a) : "l"(p));
    return a;
}
__device__ __forceinline__ void cp_async_16(uint32_t dst, const void* src) {
    asm volatile("cp.async.cg.shared.global [%0], [%1], 16;" :: "r"(dst), "l"(src));
}
#define CP_COMMIT()   asm volatile("cp.async.commit_group;" ::: "memory")
#define CP_WAIT_ALL() asm volatile("cp.async.wait_group 0;" ::: "memory")

#define LDSM_X4(r0, r1, r2, r3, addr) \
    asm volatile("ldmatrix.sync.aligned.m8n8.x4.shared.b16 {%0,%1,%2,%3}, [%4];" \
        : "=r"(r0), "=r"(r1), "=r"(r2), "=r"(r3) : "r"(addr))
#define LDSM_X4_T(r0, r1, r2, r3, addr) \
    asm volatile("ldmatrix.sync.aligned.m8n8.x4.trans.shared.b16 {%0,%1,%2,%3}, [%4];" \
        : "=r"(r0), "=r"(r1), "=r"(r2), "=r"(r3) : "r"(addr))

__device__ __forceinline__ void mma16816(float* c, const uint32_t* a, const uint32_t* b) {
    asm volatile(
        "mma.sync.aligned.m16n8k16.row.col.f32.f16.f16.f32 "
        "{%0,%1,%2,%3}, {%4,%5,%6,%7}, {%8,%9}, {%0,%1,%2,%3};"
        : "+f"(c[0]), "+f"(c[1]), "+f"(c[2]), "+f"(c[3])
        : "r"(a[0]), "r"(a[1]), "r"(a[2]), "r"(a[3]), "r"(b[0]), "r"(b[1]));
}

__device__ __forceinline__ float lrelu(float v) {
    return fmaxf(v, 0.f) + 0.01f * fminf(v, 0.f);
}

// ============================================================================
// Merged pre-pass: x fp32->fp16 (blocks [0,512)), W1 fp32->fp16 ([512,33280))
// ============================================================================
__global__ void convert_all_kernel(const float* __restrict__ x,
                                   const float* __restrict__ W1) {
    const float* src;
    __half* dst;
    size_t g;
    if (blockIdx.x < 512) {
        g = (size_t)blockIdx.x * 256 + threadIdx.x;
        src = x;  dst = g_X16;
    } else {
        g = (size_t)(blockIdx.x - 512) * 256 + threadIdx.x;
        src = W1; dst = g_W16;
    }
    const float4* p = reinterpret_cast<const float4*>(src) + g * 2;
    float4 a = p[0], b = p[1];
    __half2 h0 = __floats2half2_rn(a.x, a.y), h1 = __floats2half2_rn(a.z, a.w);
    __half2 h2 = __floats2half2_rn(b.x, b.y), h3 = __floats2half2_rn(b.z, b.w);
    uint4 o;
    o.x = *reinterpret_cast<uint32_t*>(&h0);
    o.y = *reinterpret_cast<uint32_t*>(&h1);
    o.z = *reinterpret_cast<uint32_t*>(&h2);
    o.w = *reinterpret_cast<uint32_t*>(&h3);
    *reinterpret_cast<uint4*>(dst + g * 8) = o;
}

// ============================================================================
// Main fused kernel
// Grid: 1024 = 64 heads x 16 m-tiles. 512 threads = 16 warps.
// Warps 0-7 = half 0 (n-chunks 0-7), warps 8-15 = half 1 (n-chunks 8-15).
// Each half: 4m x 2n warps, warp tile 32m x 64n, own W double buffer (16KB
// chunks), own named barrier, own cp.async groups. X tile shared (read-only).
// Folds: half 0 deferred to top of kb==0 (de-phased vs half 1's kb==7 fold).
//
// SMEM:
//   [0..131072)        X: [kb][128m][64k halves], 128B rows, swizzled
//   [131072..196608)   W: 2 halves x 2 bufs x (64k x 128n), 256B rows, swizzled
//   [196608..212992)   bw: float2[2048] = (b1, W2)
//   [212992..215040)   part: float[128][4]
// ============================================================================
#define SM_X    0
#define SM_W    131072
#define SM_BW   196608
#define SM_PART 212992
#define SMEM_TOTAL 215040
#define NTHREADS 512

__device__ __forceinline__ void fill_w_chunk(const __half* __restrict__ Wh,
                                             uint32_t sb, int half, int t, int ht) {
    int nc = half * 8 + (t >> 3);
    int kb = t & 7;
    uint32_t base = sb + SM_W + half * 32768 + (t & 1) * 16384;
    const __half* src = Wh + (size_t)(kb * 64) * HID + nc * 128;
#pragma unroll
    for (int i = 0; i < 4; ++i) {
        int idx = i * 256 + ht;                 // 1024 chunks of 16B
        int kr = idx >> 4, j = idx & 15;
        uint32_t dst = base + kr * 256 + ((j * 16) ^ ((kr & 7) << 4));
        cp_async_16(dst, src + (size_t)kr * HID + j * 8);
    }
}

// fold one completed 128-col n-chunk: bias + leaky + dot(W2); zero acc
__device__ __forceinline__ void fold_chunk(float (&acc)[2][8][4], float (&rowacc)[4],
                                           const float2* __restrict__ bw,
                                           int ncf, int wn, int lane) {
    int ncb = ncf * 128 + wn * 64 + (lane & 3) * 2;
#pragma unroll
    for (int ni = 0; ni < 8; ++ni) {
        int n = ncb + ni * 8;
        float2 p0 = bw[n];
        float2 p1 = bw[n + 1];
#pragma unroll
        for (int mi = 0; mi < 2; ++mi) {
            rowacc[mi * 2 + 0] = fmaf(lrelu(acc[mi][ni][0] + p0.x), p0.y, rowacc[mi * 2 + 0]);
            rowacc[mi * 2 + 0] = fmaf(lrelu(acc[mi][ni][1] + p1.x), p1.y, rowacc[mi * 2 + 0]);
            rowacc[mi * 2 + 1] = fmaf(lrelu(acc[mi][ni][2] + p0.x), p0.y, rowacc[mi * 2 + 1]);
            rowacc[mi * 2 + 1] = fmaf(lrelu(acc[mi][ni][3] + p1.x), p1.y, rowacc[mi * 2 + 1]);
            acc[mi][ni][0] = 0.f; acc[mi][ni][1] = 0.f;
            acc[mi][ni][2] = 0.f; acc[mi][ni][3] = 0.f;
        }
    }
}

__global__ void __launch_bounds__(NTHREADS, 1) mhmlp_main(
    const float* __restrict__ b1g, const float* __restrict__ w2g,
    const float* __restrict__ b2g, float* __restrict__ out)
{
    extern __shared__ char smem[];
    uint32_t sb = smem_to_u32(smem);
    int tid  = threadIdx.x;
    int lane = tid & 31;
    int wid  = tid >> 5;
    int half = wid >> 3;        // 0 or 1
    int hw   = wid & 7;         // warp index within half
    int wm   = hw >> 1;         // 0..3 (32-row band)
    int wn   = hw & 1;          // 0..1 (64-col half of the 128n chunk)
    int ht   = tid & 255;       // thread index within half
    int h  = blockIdx.x >> 4;
    int m0 = (blockIdx.x & 15) * 128;

    const __half* Wh = g_W16 + (size_t)h * DD * HID;

    // ---- X tile fill (all 512 threads): [kb][m][64k], swizzled 128B rows ----
#pragma unroll
    for (int i = 0; i < 16; ++i) {
        int idx = i * NTHREADS + tid;            // 8192 chunks of 16B
        int m = idx >> 6, j = idx & 63;
        int kb = j >> 3, jj = j & 7;
        uint32_t dst = sb + SM_X + kb * 16384 + m * 128 + ((jj * 16) ^ ((m & 7) << 4));
        cp_async_16(dst, g_X16 + (size_t)(m0 + m) * DD + kb * 64 + jj * 8);
    }
    // ---- each half fills its W chunk 0 ----
    fill_w_chunk(Wh, sb, half, 0, ht);
    CP_COMMIT();

    // ---- bias/W2 table into smem ----
    float2* bw = reinterpret_cast<float2*>(smem + SM_BW);
#pragma unroll
    for (int i = 0; i < 4; ++i) {
        int n = i * NTHREADS + tid;
        bw[n] = make_float2(b1g[h * HID + n], w2g[h * HID + n]);
    }
    CP_WAIT_ALL();
    __syncthreads();            // X + both W0 chunks + bw visible to all

    float acc[2][8][4];
#pragma unroll
    for (int mi = 0; mi < 2; ++mi)
#pragma unroll
        for (int ni = 0; ni < 8; ++ni)
#pragma unroll
            for (int r = 0; r < 4; ++r) acc[mi][ni][r] = 0.f;
    float rowacc[4] = {0.f, 0.f, 0.f, 0.f};

    int la = lane & 15;
    int lb = lane >> 4;
    int lmask = (lane & 7) << 4;
    int barid = 1 + half;

    uint32_t fa[2][4];
    uint32_t fb[4][4];

    for (int t = 0; t < 64; ++t) {
        // W(t) ready: it was committed at top of t-1 (or init for t=0)
        CP_WAIT_ALL();
        asm volatile("bar.sync %0, %1;" :: "r"(barid), "r"(256) : "memory");
        // prefetch W(t+1) into the buffer whose reads finished at t-1
        if (t + 1 < 64) fill_w_chunk(Wh, sb, half, t + 1, ht);
        CP_COMMIT();

        int nc = half * 8 + (t >> 3);
        int kb = t & 7;
        uint32_t abase = sb + SM_X + kb * 16384;
        uint32_t bbase = sb + SM_W + half * 32768 + (t & 1) * 16384;

        // half 0: deferred fold of the PREVIOUS chunk at top of kb==0.
        // De-phased vs half 1's kb==7 fold -> lumps never coincide; the other
        // half's pure-MMA stream keeps the tensor pipe fed.
        if (half == 0 && kb == 0 && t > 0)
            fold_chunk(acc, rowacc, bw, nc - 1, wn, lane);

#pragma unroll
        for (int ks = 0; ks < 4; ++ks) {
#pragma unroll
            for (int mi = 0; mi < 2; ++mi) {
                int m = wm * 32 + mi * 16 + la;
                uint32_t ad = abase + m * 128 + ((ks * 32 + lb * 16) ^ lmask);
                LDSM_X4(fa[mi][0], fa[mi][1], fa[mi][2], fa[mi][3], ad);
            }
#pragma unroll
            for (int nb = 0; nb < 4; ++nb) {
                int kr = ks * 16 + la;
                uint32_t bd = bbase + kr * 256 +
                              (((wn * 64 + nb * 16 + lb * 8) * 2) ^ lmask);
                LDSM_X4_T(fb[nb][0], fb[nb][1], fb[nb][2], fb[nb][3], bd);
            }
#pragma unroll
            for (int mi = 0; mi < 2; ++mi)
#pragma unroll
                for (int ni = 0; ni < 8; ++ni)
                    mma16816(acc[mi][ni], fa[mi], &fb[ni >> 1][(ni & 1) * 2]);
        }

        // half 1: immediate fold at bottom of kb==7 (champion schedule)
        if (half == 1 && kb == 7)
            fold_chunk(acc, rowacc, bw, nc, wn, lane);
    }
    // half 0: fold its final chunk (nc = 7)
    if (half == 0)
        fold_chunk(acc, rowacc, bw, 7, wn, lane);

    // ---- reduce rowacc across the 4 lanes sharing each row ----
#pragma unroll
    for (int i = 0; i < 4; ++i) {
        rowacc[i] += __shfl_xor_sync(0xffffffffu, rowacc[i], 1);
        rowacc[i] += __shfl_xor_sync(0xffffffffu, rowacc[i], 2);
    }
    float* part = reinterpret_cast<float*>(smem + SM_PART);
    if ((lane & 3) == 0) {
        int rq = lane >> 2;                   // 0..7
        int rbase = wm * 32;
        int col = half * 2 + wn;
        part[(rbase +  0 + rq) * 4 + col] = rowacc[0];
        part[(rbase +  8 + rq) * 4 + col] = rowacc[1];
        part[(rbase + 16 + rq) * 4 + col] = rowacc[2];
        part[(rbase + 24 + rq) * 4 + col] = rowacc[3];
    }
    __syncthreads();
    if (tid < 128) {
        float s = part[tid * 4] + part[tid * 4 + 1] + part[tid * 4 + 2] +
                  part[tid * 4 + 3] + b2g[h];
        s = lrelu(s);
        out[(size_t)(m0 + tid) * HH + h] = s;
    }
}

// ============================================================================
// Launch
// ============================================================================
extern "C" void kernel_launch(void* const* d_in, const int* in_sizes, int n_in,
                              void* d_out, int out_size) {
    const float* x  = (const float*)d_in[0];
    const float* W1 = (const float*)d_in[1];
    const float* b1 = (const float*)d_in[2];
    const float* W2 = (const float*)d_in[3];
    const float* b2 = (const float*)d_in[4];
    float* out = (float*)d_out;

    convert_all_kernel<<<33280, 256>>>(x, W1);

    cudaFuncSetAttribute(mhmlp_main, cudaFuncAttributeMaxDynamicSharedMemorySize, SMEM_TOTAL);
    mhmlp_main<<<1024, NTHREADS, SMEM_TOTAL>>>(b1, W2, b2, out);
}

// round 17
// speedup vs baseline: 1.0118x; 1.0118x over previous
#include <cuda_runtime.h>
#include <cuda_fp16.h>
#include <cstdint>

// ============================================================================
// MHMLP: out[b,h] = lrelu( sum_n lrelu( x[b,:]·W1[h,:,n] + b1[h,n] ) * W2[h,n] + b2[h] )
// B=2048, H=64, D=512(K), HID=2048(N). fp32 in/out, fp16 HMMA compute.
// FINAL CHAMPION (R5, reconfirmed R15): one CTA = two independent pipeline
// halves (split by n, own W double buffers, own named barriers, own cp.async
// groups). 16 warps, warp tile 32m x 64n, 64 iterations of 128n x 64k.
// Session-measured optimum: quarters / triple-buffer / 64x64 tiles / split
// barriers / fp16-acc / fused-convert / persistent / occupancy-2 / de-phased
// folds ALL regressed or were neutral vs this configuration.
// ============================================================================
#define BB   2048
#define HH   64
#define DD   512
#define HID  2048

__device__ __half  g_W16[(size_t)HH * DD * HID];    // [h][d][n] fp16
__device__ __half  g_X16[(size_t)BB * DD];          // [b][d]   fp16
__device__ float4  g_BW4[(size_t)HH * HID / 2];     // {b1[n],w2[n],b1[n+1],w2[n+1]}

__device__ __forceinline__ uint32_t smem_to_u32(const void* p) {
    uint32_t a;
    asm("{ .reg .u64 t; cvta.to.shared.u64 t, %1; cvt.u32.u64 %0, t; }" : "=r"(a) : "l"(p));
    return a;
}
__device__ __forceinline__ void cp_async_16(uint32_t dst, const void* src) {
    asm volatile("cp.async.cg.shared.global [%0], [%1], 16;" :: "r"(dst), "l"(src));
}
#define CP_COMMIT()   asm volatile("cp.async.commit_group;" ::: "memory")
#define CP_WAIT_ALL() asm volatile("cp.async.wait_group 0;" ::: "memory")

#define LDSM_X4(r0, r1, r2, r3, addr) \
    asm volatile("ldmatrix.sync.aligned.m8n8.x4.shared.b16 {%0,%1,%2,%3}, [%4];" \
        : "=r"(r0), "=r"(r1), "=r"(r2), "=r"(r3) : "r"(addr))
#define LDSM_X4_T(r0, r1, r2, r3, addr) \
    asm volatile("ldmatrix.sync.aligned.m8n8.x4.trans.shared.b16 {%0,%1,%2,%3}, [%4];" \
        : "=r"(r0), "=r"(r1), "=r"(r2), "=r"(r3) : "r"(addr))

__device__ __forceinline__ void mma16816(float* c, const uint32_t* a, const uint32_t* b) {
    asm volatile(
        "mma.sync.aligned.m16n8k16.row.col.f32.f16.f16.f32 "
        "{%0,%1,%2,%3}, {%4,%5,%6,%7}, {%8,%9}, {%0,%1,%2,%3};"
        : "+f"(c[0]), "+f"(c[1]), "+f"(c[2]), "+f"(c[3])
        : "r"(a[0]), "r"(a[1]), "r"(a[2]), "r"(a[3]), "r"(b[0]), "r"(b[1]));
}

__device__ __forceinline__ float lrelu(float v) {
    return fmaxf(v, 0.f) + 0.01f * fminf(v, 0.f);
}

// ============================================================================
// Merged pre-pass:
//   blocks [0,512):       x fp32 -> fp16
//   blocks [512,33280):   W1 fp32 -> fp16
//   blocks [33280,33312): build g_BW4 (b1/W2 interleaved)
// ============================================================================
__global__ void convert_all_kernel(const float* __restrict__ x,
                                   const float* __restrict__ W1,
                                   const float* __restrict__ b1,
                                   const float* __restrict__ w2) {
    if (blockIdx.x >= 33280) {
        int g = (blockIdx.x - 33280) * 256 + threadIdx.x;   // 8192 threads
        float2* bw2 = reinterpret_cast<float2*>(g_BW4);
#pragma unroll
        for (int i = 0; i < 16; ++i) {
            int e = g + i * 8192;                           // HH*HID = 131072
            bw2[e] = make_float2(b1[e], w2[e]);
        }
        return;
    }
    const float* src;
    __half* dst;
    size_t g;
    if (blockIdx.x < 512) {
        g = (size_t)blockIdx.x * 256 + threadIdx.x;
        src = x;  dst = g_X16;
    } else {
        g = (size_t)(blockIdx.x - 512) * 256 + threadIdx.x;
        src = W1; dst = g_W16;
    }
    const float4* p = reinterpret_cast<const float4*>(src) + g * 2;
    float4 a = p[0], b = p[1];
    __half2 h0 = __floats2half2_rn(a.x, a.y), h1 = __floats2half2_rn(a.z, a.w);
    __half2 h2 = __floats2half2_rn(b.x, b.y), h3 = __floats2half2_rn(b.z, b.w);
    uint4 o;
    o.x = *reinterpret_cast<uint32_t*>(&h0);
    o.y = *reinterpret_cast<uint32_t*>(&h1);
    o.z = *reinterpret_cast<uint32_t*>(&h2);
    o.w = *reinterpret_cast<uint32_t*>(&h3);
    *reinterpret_cast<uint4*>(dst + g * 8) = o;
}

// ============================================================================
// Main fused kernel
// Grid: 1024 = 64 heads x 16 m-tiles. 512 threads = 16 warps.
// Warps 0-7 = half 0 (n-chunks 0-7), warps 8-15 = half 1 (n-chunks 8-15).
// Each half: 4m x 2n warps, warp tile 32m x 64n, own W double buffer (16KB
// chunks), own named barrier, own cp.async groups. X tile shared (read-only).
//
// SMEM:
//   [0..131072)        X: [kb][128m][64k halves], 128B rows, swizzled
//   [131072..196608)   W: 2 halves x 2 bufs x (64k x 128n), 256B rows, swizzled
//   [196608..198656)   part: float[128][4]
// ============================================================================
#define SM_X    0
#define SM_W    131072
#define SM_PART 196608
#define SMEM_TOTAL 198656
#define NTHREADS 512

__device__ __forceinline__ void fill_w_chunk(const __half* __restrict__ Wh,
                                             uint32_t sb, int half, int t, int ht) {
    int nc = half * 8 + (t >> 3);
    int kb = t & 7;
    uint32_t base = sb + SM_W + half * 32768 + (t & 1) * 16384;
    const __half* src = Wh + (size_t)(kb * 64) * HID + nc * 128;
#pragma unroll
    for (int i = 0; i < 4; ++i) {
        int idx = i * 256 + ht;                 // 1024 chunks of 16B
        int kr = idx >> 4, j = idx & 15;
        uint32_t dst = base + kr * 256 + ((j * 16) ^ ((kr & 7) << 4));
        cp_async_16(dst, src + (size_t)kr * HID + j * 8);
    }
}

__global__ void __launch_bounds__(NTHREADS, 1) mhmlp_main(
    const float* __restrict__ b2g, float* __restrict__ out)
{
    extern __shared__ char smem[];
    uint32_t sb = smem_to_u32(smem);
    int tid  = threadIdx.x;
    int lane = tid & 31;
    int wid  = tid >> 5;
    int half = wid >> 3;        // 0 or 1
    int hw   = wid & 7;         // warp index within half
    int wm   = hw >> 1;         // 0..3 (32-row band)
    int wn   = hw & 1;          // 0..1 (64-col half of the 128n chunk)
    int ht   = tid & 255;       // thread index within half
    int h  = blockIdx.x >> 4;
    int m0 = (blockIdx.x & 15) * 128;

    const __half* Wh = g_W16 + (size_t)h * DD * HID;

    // ---- X tile fill (all 512 threads): [kb][m][64k], swizzled 128B rows ----
#pragma unroll
    for (int i = 0; i < 16; ++i) {
        int idx = i * NTHREADS + tid;            // 8192 chunks of 16B
        int m = idx >> 6, j = idx & 63;
        int kb = j >> 3, jj = j & 7;
        uint32_t dst = sb + SM_X + kb * 16384 + m * 128 + ((jj * 16) ^ ((m & 7) << 4));
        cp_async_16(dst, g_X16 + (size_t)(m0 + m) * DD + kb * 64 + jj * 8);
    }
    // ---- each half fills its W chunk 0 ----
    fill_w_chunk(Wh, sb, half, 0, ht);
    CP_COMMIT();
    CP_WAIT_ALL();
    __syncthreads();            // X + both W0 chunks visible to all

    float acc[2][8][4];
#pragma unroll
    for (int mi = 0; mi < 2; ++mi)
#pragma unroll
        for (int ni = 0; ni < 8; ++ni)
#pragma unroll
            for (int r = 0; r < 4; ++r) acc[mi][ni][r] = 0.f;
    float rowacc[4] = {0.f, 0.f, 0.f, 0.f};

    int la = lane & 15;
    int lb = lane >> 4;
    int lmask = (lane & 7) << 4;
    int barid = 1 + half;
    const float4* bw4 = g_BW4 + (size_t)h * (HID / 2);

    uint32_t fa[2][4];
    uint32_t fb[4][4];

    for (int t = 0; t < 64; ++t) {
        // W(t) ready: it was committed at top of t-1 (or init for t=0)
        CP_WAIT_ALL();
        asm volatile("bar.sync %0, %1;" :: "r"(barid), "r"(256) : "memory");
        // prefetch W(t+1) into the buffer whose reads finished at t-1
        if (t + 1 < 64) fill_w_chunk(Wh, sb, half, t + 1, ht);
        CP_COMMIT();

        int nc = half * 8 + (t >> 3);
        int kb = t & 7;
        uint32_t abase = sb + SM_X + kb * 16384;
        uint32_t bbase = sb + SM_W + half * 32768 + (t & 1) * 16384;

#pragma unroll
        for (int ks = 0; ks < 4; ++ks) {
#pragma unroll
            for (int mi = 0; mi < 2; ++mi) {
                int m = wm * 32 + mi * 16 + la;
                uint32_t ad = abase + m * 128 + ((ks * 32 + lb * 16) ^ lmask);
                LDSM_X4(fa[mi][0], fa[mi][1], fa[mi][2], fa[mi][3], ad);
            }
#pragma unroll
            for (int nb = 0; nb < 4; ++nb) {
                int kr = ks * 16 + la;
                uint32_t bd = bbase + kr * 256 +
                              (((wn * 64 + nb * 16 + lb * 8) * 2) ^ lmask);
                LDSM_X4_T(fb[nb][0], fb[nb][1], fb[nb][2], fb[nb][3], bd);
            }
#pragma unroll
            for (int mi = 0; mi < 2; ++mi)
#pragma unroll
                for (int ni = 0; ni < 8; ++ni)
                    mma16816(acc[mi][ni], fa[mi], &fb[ni >> 1][(ni & 1) * 2]);
        }

        if (kb == 7) {
            // fold 128-col n-chunk: bias + leaky + dot(W2); bw from L2-hot global
            int fbase = nc * 64 + wn * 32 + (lane & 3);   // float4 index
#pragma unroll
            for (int ni = 0; ni < 8; ++ni) {
                float4 v = bw4[fbase + ni * 4];           // {b1,w2,b1',w2'}
#pragma unroll
                for (int mi = 0; mi < 2; ++mi) {
                    rowacc[mi * 2 + 0] = fmaf(lrelu(acc[mi][ni][0] + v.x), v.y, rowacc[mi * 2 + 0]);
                    rowacc[mi * 2 + 0] = fmaf(lrelu(acc[mi][ni][1] + v.z), v.w, rowacc[mi * 2 + 0]);
                    rowacc[mi * 2 + 1] = fmaf(lrelu(acc[mi][ni][2] + v.x), v.y, rowacc[mi * 2 + 1]);
                    rowacc[mi * 2 + 1] = fmaf(lrelu(acc[mi][ni][3] + v.z), v.w, rowacc[mi * 2 + 1]);
                    acc[mi][ni][0] = 0.f; acc[mi][ni][1] = 0.f;
                    acc[mi][ni][2] = 0.f; acc[mi][ni][3] = 0.f;
                }
            }
        }
    }

    // ---- reduce rowacc across the 4 lanes sharing each row ----
#pragma unroll
    for (int i = 0; i < 4; ++i) {
        rowacc[i] += __shfl_xor_sync(0xffffffffu, rowacc[i], 1);
        rowacc[i] += __shfl_xor_sync(0xffffffffu, rowacc[i], 2);
    }
    float* part = reinterpret_cast<float*>(smem + SM_PART);
    if ((lane & 3) == 0) {
        int rq = lane >> 2;                   // 0..7
        int rbase = wm * 32;
        int col = half * 2 + wn;
        part[(rbase +  0 + rq) * 4 + col] = rowacc[0];
        part[(rbase +  8 + rq) * 4 + col] = rowacc[1];
        part[(rbase + 16 + rq) * 4 + col] = rowacc[2];
        part[(rbase + 24 + rq) * 4 + col] = rowacc[3];
    }
    __syncthreads();
    if (tid < 128) {
        float s = part[tid * 4] + part[tid * 4 + 1] + part[tid * 4 + 2] +
                  part[tid * 4 + 3] + b2g[h];
        s = lrelu(s);
        out[(size_t)(m0 + tid) * HH + h] = s;
    }
}

// ============================================================================
// Launch
// ============================================================================
extern "C" void kernel_launch(void* const* d_in, const int* in_sizes, int n_in,
                              void* d_out, int out_size) {
    const float* x  = (const float*)d_in[0];
    const float* W1 = (const float*)d_in[1];
    const float* b1 = (const float*)d_in[2];
    const float* W2 = (const float*)d_in[3];
    const float* b2 = (const float*)d_in[4];
    float* out = (float*)d_out;

    convert_all_kernel<<<33312, 256>>>(x, W1, b1, W2);

    cudaFuncSetAttribute(mhmlp_main, cudaFuncAttributeMaxDynamicSharedMemorySize, SMEM_TOTAL);
    mhmlp_main<<<1024, NTHREADS, SMEM_TOTAL>>>(b2, out);
}